// round 14
// baseline (speedup 1.0000x reference)
#include <cuda_runtime.h>
#include <cstdint>
#include <cstddef>

// RWW whole-brain sim, 8-CTA cluster, Con_Mtx register-resident.
// R14 = R13 (per-stripe warp-uniform waits, champion) with the exchange
//       switched from 7x256B S2S bulk copies (serial engine injection tail
//       ~400 cyc) to ONE multicast bulk copy per CTA per step:
//   - epilogue threads st.global.cg their 64 new S_E into __device__ L2
//     scratch; one thread issues cp.async.bulk.shared::cluster.global
//     .mbarrier::complete_tx::bytes.multicast::cluster (mask 0xFF), which
//     delivers data + tx to the same smem offset / same mbarrier in ALL
//     8 CTAs simultaneously (self included -> staging/LB machinery gone).
//   - everything else identical to R13 (bit-identical arithmetic).

#define NREG    512
#define NSTEPS  20000
#define NCTAS   8
#define NTHR    512

// smem byte map
#define X_OFF    0        // x[2][512] floats          (4096 B)
#define SUM_OFF  4096     // sums[2][512] floats       (4096 B)
#define MB_OFF   8192     // 16 src mbarriers [buf][src] (128 B)
#define SMEM_BYTES 8448

// L2-resident exchange scratch (device global: allocation-free)
__device__ __align__(256) float g_xbuf[2][NREG];

__device__ __forceinline__ unsigned long long ffma2(
    unsigned long long a, unsigned long long b, unsigned long long c) {
    unsigned long long d;
    asm("fma.rn.f32x2 %0, %1, %2, %3;" : "=l"(d) : "l"(a), "l"(b), "l"(c));
    return d;
}
__device__ __forceinline__ float fsum2(unsigned long long a) {
    float2 f = *reinterpret_cast<float2*>(&a);
    return f.x + f.y;
}
__device__ __forceinline__ void mbar_wait(uint32_t mb, uint32_t par) {
    asm volatile(
        "{\n\t"
        ".reg .pred P;\n"
        "WL_%=:\n\t"
        "mbarrier.try_wait.parity.acquire.cluster.shared::cta.b64 P, [%0], %1, 0x989680;\n\t"
        "@!P bra WL_%=;\n\t"
        "}" :: "r"(mb), "r"(par) : "memory");
}

__device__ __forceinline__ float Hfun(float I, float a, float b, float d, float bigc) {
    float x     = fmaf(a, I, -b);
    float numer = fabsf(x) + 1e-9f;
    float neg   = -d * x;
    float e     = __expf(fminf(neg, 51.0f));
    float den_s = fabsf(1.0f - e) + 1e-9f * d;
    float den_b = fabsf(1.0f - bigc * neg) + 1e-9f * d;
    float denom = (neg > 50.0f) ? den_b : den_s;
    return __fdividef(numer, denom);
}

extern __shared__ float smx[];

__global__ void __launch_bounds__(NTHR, 1) __cluster_dims__(NCTAS, 1, 1)
rww_kernel(const float* __restrict__ init_state,   // (512, 2)
           const float* __restrict__ Con,          // (512, 512) row-major
           const float* __restrict__ vofT,         // (20000, 512)
           float* __restrict__ out)                // 1024 final + 20000*1024 hist
{
    const int tid  = (int)threadIdx.x;
    const int cta  = (int)blockIdx.x;          // cluster rank
    const int lane = tid & 31;
    const int w    = tid >> 5;                 // warp 0..15
    const int q    = w & 7;                    // stripe (source CTA) of warp
    const int rmv  = ((w >> 3) << 5) + lane;   // matvec row 0..63

    const bool epi  = (tid >= 448);            // warps 14-15: epilogue
    const int  erow = tid - 448;               // epilogue row 0..63

    uint32_t sb;
    asm("{ .reg .u64 t; cvta.to.shared.u64 t, %1; cvt.u32.u64 %0, t; }"
        : "=r"(sb) : "l"(smx));

    // ---- 16 src mbarriers [buf][src]: count=1, phase-0 tx armed ----
    if (tid < 16) {
        uint32_t mb = sb + MB_OFF + (uint32_t)(tid * 8);
        asm volatile("mbarrier.init.shared.b64 [%0], %1;" :: "r"(mb), "r"(1));
        asm volatile("mbarrier.arrive.expect_tx.shared.b64 _, [%0], %1;"
                     :: "r"(mb), "r"(256) : "memory");
    }

    // ---- Con: row cta*64+rmv, cols q*64..q*64+63 -> 32 f32x2 regs ----
    unsigned long long c64[32];
    {
        const ulonglong2* src = (const ulonglong2*)
            (Con + (size_t)(cta * 64 + rmv) * NREG + (size_t)q * 64);
        #pragma unroll
        for (int it = 0; it < 16; ++it) {
            ulonglong2 t2 = src[it];
            c64[2*it] = t2.x; c64[2*it+1] = t2.y;
        }
    }

    // ---- init x buffer 0 (contiguous; warp reads are broadcast) ----
    if (tid < NREG) smx[tid] = init_state[2 * tid];

    // ---- epilogue state (row = erow) ----
    float sE = 0.0f, sI = 0.0f;
    if (epi) {
        sE = init_state[2 * (cta * 64 + erow)];
        sI = init_state[2 * (cta * 64 + erow) + 1];
    }

    __syncthreads();
    asm volatile("barrier.cluster.arrive.aligned;" ::: "memory");
    asm volatile("barrier.cluster.wait.aligned;"   ::: "memory");

    float vc = 0.0f, vn = 0.0f;
    if (epi) {
        vc = __ldg(vofT + cta * 64 + erow);
        vn = __ldg(vofT + NREG + cta * 64 + erow);
    }
    float2* outv = (float2*)out;

    int pb0 = 0, pb1 = 0;     // wait parity of my stripe barrier, per buf

    for (int t = 0; t < NSTEPS; ++t) {
        const int b = t & 1;

        // ---- hoisted, bit-identical rI chain (no network term) ----
        float rI = 0.0f;
        if (epi) {
            float I_I = 0.2674f + 0.15f * sE - sI;
            rI = Hfun(I_I, 615.0f, 177.0f, 0.087f, 1e5f);
        }

        // ---- per-warp per-stripe wait (uniform in-warp), all 8 stripes ----
        if (t) {
            uint32_t mb = sb + MB_OFF + (uint32_t)((b * 8 + q) * 8);
            if (b) { mbar_wait(mb, (uint32_t)pb1); pb1 ^= 1; }
            else   { mbar_wait(mb, (uint32_t)pb0); pb0 ^= 1; }
            if (lane == 0 && w < 8)   // one re-arm per barrier
                asm volatile("mbarrier.arrive.expect_tx.shared.b64 _, [%0], %1;"
                             :: "r"(mb), "r"(256) : "memory");
        }

        // ---- matvec: 64 cols of stripe q (broadcast LDS), row rmv ----
        const ulonglong2* x2 = (const ulonglong2*)
            ((const char*)smx + X_OFF + b * 2048 + q * 256);
        unsigned long long a0 = 0ULL, a1 = 0ULL, a2 = 0ULL, a3 = 0ULL;
        #pragma unroll
        for (int it = 0; it < 8; ++it) {
            ulonglong2 xa = x2[2*it];
            ulonglong2 xb = x2[2*it+1];
            a0 = ffma2(c64[4*it+0], xa.x, a0);
            a1 = ffma2(c64[4*it+1], xa.y, a1);
            a2 = ffma2(c64[4*it+2], xb.x, a2);
            a3 = ffma2(c64[4*it+3], xb.y, a3);
        }
        // partial for (row rmv, stripe q) -> sums[b][q*64 + rmv]
        smx[(SUM_OFF + b * 2048) / 4 + q * 64 + rmv] =
            (fsum2(a0) + fsum2(a1)) + (fsum2(a2) + fsum2(a3));

        __syncthreads();   // all stripes' partials visible

        if (epi) {
            // ---- reduce 8 partials for my row (same tree as R13) ----
            const float* su = smx + (SUM_OFF + b * 2048) / 4 + erow;
            float p0 = su[0*64], p1 = su[1*64], p2 = su[2*64], p3 = su[3*64];
            float p4 = su[4*64], p5 = su[5*64], p6 = su[6*64], p7 = su[7*64];
            float acc = ((p0 + p1) + (p2 + p3)) + ((p4 + p5) + (p6 + p7));

            // ---- epilogue: EXACT R13 expressions ----
            float I_E = 0.382f  + 0.21f * sE + 3.0f * acc - sI;  // LAMBDA=0
            float rE = Hfun(I_E, 310.0f, 125.0f, 0.16f,  1e9f);
            float dE = -sE * 0.01f + (1.0f - sE) * 6.41e-4f * rE + 0.01f * vc;
            float dI = -sI * 0.1f  + 1.0e-3f * rI + 0.01f * vc;
            sE = fmaf(1e-4f, dE, sE);
            sI = fmaf(1e-4f, dI, sI);

            // ---- publish new S_E to L2 scratch (bypass L1) ----
            if (t + 1 < NSTEPS)
                __stcg(&g_xbuf[b][cta * 64 + erow], sE);

            asm volatile("bar.sync 1, 64;" ::: "memory");   // stripe staged

            // ---- ONE multicast bulk copy: data + tx to ALL 8 CTAs ----
            if (tid == 448 && (t + 1 < NSTEPS)) {
                asm volatile("fence.proxy.async;" ::: "memory");
                uint32_t dst = sb + (uint32_t)(X_OFF + (b ^ 1) * 2048 + cta * 256);
                uint32_t mbr = sb + (uint32_t)(MB_OFF + (((b ^ 1) * 8) + cta) * 8);
                const float* src = &g_xbuf[b][cta * 64];
                asm volatile(
                    "cp.async.bulk.shared::cluster.global.mbarrier::complete_tx::bytes"
                    ".multicast::cluster [%0], [%1], %2, [%3], %4;"
                    :: "r"(dst), "l"(src), "r"(256), "r"(mbr),
                       "h"((unsigned short)0xFF) : "memory");
            }

            // off critical path: history + next noise
            outv[512 + (size_t)t * NREG + cta * 64 + erow] = make_float2(sE, sI);
            vc = vn;
            int t2 = t + 2; if (t2 >= NSTEPS) t2 = NSTEPS - 1;
            vn = __ldg(vofT + (size_t)t2 * NREG + cta * 64 + erow);
        }
    }

    if (epi) outv[cta * 64 + erow] = make_float2(sE, sI);

    // drain: nobody exits while peers may still receive our multicast
    asm volatile("barrier.cluster.arrive.aligned;" ::: "memory");
    asm volatile("barrier.cluster.wait.aligned;"   ::: "memory");
}

extern "C" void kernel_launch(void* const* d_in, const int* in_sizes, int n_in,
                              void* d_out, int out_size) {
    const float* init = nullptr;
    const float* con  = nullptr;
    const float* v    = nullptr;
    for (int i = 0; i < n_in; ++i) {
        if      (in_sizes[i] == NREG * 2)      init = (const float*)d_in[i];
        else if (in_sizes[i] == NREG * NREG)   con  = (const float*)d_in[i];
        else if (in_sizes[i] == NSTEPS * NREG) v    = (const float*)d_in[i];
    }
    rww_kernel<<<NCTAS, NTHR, SMEM_BYTES>>>(init, con, v, (float*)d_out);
    (void)out_size;
}

// round 16
// speedup vs baseline: 1.7600x; 1.7600x over previous
#include <cuda_runtime.h>
#include <cstdint>
#include <cstddef>

// RWW whole-brain sim, 8-CTA cluster, Con_Mtx register-resident.
// R16 = R13 (champion) + deadlock-FREE producer/consumer split:
//   - TWO alternating named barriers (2+b): producers (warps 0-13)
//     bar.arrive and sprint to their next mbarrier wait; consumers
//     (warps 14-15) bar.sync. Alternation prevents the R15 hang
//     (double-arrival in one phase by a fast producer).
//   - stripe-barrier re-arm after the partial STS (off the hot path).
//   - everything else EXACTLY R13 (bit-identical arithmetic).

#define NREG    512
#define NSTEPS  20000
#define NCTAS   8
#define NTHR    512

// smem byte map
#define X_OFF    0        // x[2][512] floats          (4096 B)
#define SUM_OFF  4096     // sums[2][512] floats       (4096 B)
#define STG_OFF  8192     // staging[2][64] floats     (512 B)
#define MB_OFF   8704     // 16 src mbarriers          (128 B)
#define LB_OFF   8832     // 2 local mbarriers         (16 B)
#define SMEM_BYTES 8960

__device__ __forceinline__ unsigned long long ffma2(
    unsigned long long a, unsigned long long b, unsigned long long c) {
    unsigned long long d;
    asm("fma.rn.f32x2 %0, %1, %2, %3;" : "=l"(d) : "l"(a), "l"(b), "l"(c));
    return d;
}
__device__ __forceinline__ float fsum2(unsigned long long a) {
    float2 f = *reinterpret_cast<float2*>(&a);
    return f.x + f.y;
}
__device__ __forceinline__ void mbar_wait(uint32_t mb, uint32_t par) {
    asm volatile(
        "{\n\t"
        ".reg .pred P;\n"
        "WL_%=:\n\t"
        "mbarrier.try_wait.parity.acquire.cluster.shared::cta.b64 P, [%0], %1, 0x989680;\n\t"
        "@!P bra WL_%=;\n\t"
        "}" :: "r"(mb), "r"(par) : "memory");
}

__device__ __forceinline__ float Hfun(float I, float a, float b, float d, float bigc) {
    float x     = fmaf(a, I, -b);
    float numer = fabsf(x) + 1e-9f;
    float neg   = -d * x;
    float e     = __expf(fminf(neg, 51.0f));
    float den_s = fabsf(1.0f - e) + 1e-9f * d;
    float den_b = fabsf(1.0f - bigc * neg) + 1e-9f * d;
    float denom = (neg > 50.0f) ? den_b : den_s;
    return __fdividef(numer, denom);
}

extern __shared__ float smx[];

__global__ void __launch_bounds__(NTHR, 1) __cluster_dims__(NCTAS, 1, 1)
rww_kernel(const float* __restrict__ init_state,   // (512, 2)
           const float* __restrict__ Con,          // (512, 512) row-major
           const float* __restrict__ vofT,         // (20000, 512)
           float* __restrict__ out)                // 1024 final + 20000*1024 hist
{
    const int tid  = (int)threadIdx.x;
    const int cta  = (int)blockIdx.x;          // cluster rank
    const int lane = tid & 31;
    const int w    = tid >> 5;                 // warp 0..15
    const int q    = w & 7;                    // stripe (source CTA) of warp
    const int rmv  = ((w >> 3) << 5) + lane;   // matvec row 0..63
    const bool isLocal = (q == cta);

    const bool epi  = (tid >= 448);            // warps 14-15: epilogue
    const int  erow = tid - 448;               // epilogue row 0..63

    uint32_t sb;
    asm("{ .reg .u64 t; cvta.to.shared.u64 t, %1; cvt.u32.u64 %0, t; }"
        : "=r"(sb) : "l"(smx));

    // ---- 16 src mbarriers [buf][src]: count=1, phase-0 tx armed ----
    if (tid < 16) {
        uint32_t mb = sb + MB_OFF + (uint32_t)(tid * 8);
        asm volatile("mbarrier.init.shared.b64 [%0], %1;" :: "r"(mb), "r"(1));
        asm volatile("mbarrier.arrive.expect_tx.shared.b64 _, [%0], %1;"
                     :: "r"(mb), "r"(256) : "memory");
    }
    // ---- 2 local mbarriers (staging guards), count=1 ----
    if (tid == 16) {
        asm volatile("mbarrier.init.shared.b64 [%0], %1;" :: "r"(sb + LB_OFF), "r"(1));
        asm volatile("mbarrier.init.shared.b64 [%0], %1;" :: "r"(sb + LB_OFF + 8), "r"(1));
    }

    // ---- Con: row cta*64+rmv, cols q*64..q*64+63 -> 32 f32x2 regs ----
    unsigned long long c64[32];
    {
        const ulonglong2* src = (const ulonglong2*)
            (Con + (size_t)(cta * 64 + rmv) * NREG + (size_t)q * 64);
        #pragma unroll
        for (int it = 0; it < 16; ++it) {
            ulonglong2 t2 = src[it];
            c64[2*it] = t2.x; c64[2*it+1] = t2.y;
        }
    }

    // ---- init x buffer 0 (contiguous; warp reads are broadcast) ----
    if (tid < NREG) smx[tid] = init_state[2 * tid];

    // ---- epilogue state (row = erow) + staging[1] bootstrap ----
    float sE = 0.0f, sI = 0.0f;
    if (epi) {
        sE = init_state[2 * (cta * 64 + erow)];
        sI = init_state[2 * (cta * 64 + erow) + 1];
        smx[(STG_OFF + 256) / 4 + erow] = sE;   // staging[1] for t=0 self-read
    }

    // ---- copy threads (tid 448..454): peer smem bases ----
    uint32_t remB = 0;
    if (tid >= 448 && tid < 455) {
        int d = tid - 448;
        int dest = d + (d >= cta ? 1 : 0);
        asm("mapa.shared::cluster.u32 %0, %1, %2;" : "=r"(remB) : "r"(sb), "r"(dest));
    }

    __syncthreads();
    asm volatile("barrier.cluster.arrive.aligned;" ::: "memory");
    asm volatile("barrier.cluster.wait.aligned;"   ::: "memory");

    float vc = 0.0f, vn = 0.0f;
    if (epi) {
        vc = __ldg(vofT + cta * 64 + erow);
        vn = __ldg(vofT + NREG + cta * 64 + erow);
    }
    float2* outv = (float2*)out;

    int pb0 = 0, pb1 = 0;     // parities: src barrier per buf (non-local warps)
    int pl0 = 0, pl1 = 0;     // parities: local barrier per buf (local warps)

    for (int t = 0; t < NSTEPS; ++t) {
        const int b = t & 1;

        // ---- hoisted, bit-identical rI chain (no network term) ----
        float rI = 0.0f;
        if (epi) {
            float I_I = 0.2674f + 0.15f * sE - sI;
            rI = Hfun(I_I, 615.0f, 177.0f, 0.087f, 1e5f);
        }

        // ---- per-warp wait (uniform in-warp) ----
        uint32_t mbq = 0;
        if (t) {
            if (!isLocal) {
                mbq = sb + MB_OFF + (uint32_t)((b * 8 + q) * 8);
                if (b) { mbar_wait(mbq, (uint32_t)pb1); pb1 ^= 1; }
                else   { mbar_wait(mbq, (uint32_t)pb0); pb0 ^= 1; }
            } else {
                uint32_t lb = sb + LB_OFF + (uint32_t)((b ^ 1) * 8);
                if (b ^ 1) { mbar_wait(lb, (uint32_t)pl1); pl1 ^= 1; }
                else       { mbar_wait(lb, (uint32_t)pl0); pl0 ^= 1; }
            }
        }

        // ---- matvec: 64 cols of stripe q (broadcast LDS), row rmv ----
        const ulonglong2* x2 = isLocal
            ? (const ulonglong2*)((const char*)smx + STG_OFF + (b ^ 1) * 256)
            : (const ulonglong2*)((const char*)smx + X_OFF + b * 2048 + q * 256);
        unsigned long long a0 = 0ULL, a1 = 0ULL, a2 = 0ULL, a3 = 0ULL;
        #pragma unroll
        for (int it = 0; it < 8; ++it) {
            ulonglong2 xa = x2[2*it];
            ulonglong2 xb = x2[2*it+1];
            a0 = ffma2(c64[4*it+0], xa.x, a0);
            a1 = ffma2(c64[4*it+1], xa.y, a1);
            a2 = ffma2(c64[4*it+2], xb.x, a2);
            a3 = ffma2(c64[4*it+3], xb.y, a3);
        }
        // partial for (row rmv, stripe q) -> sums[b][q*64 + rmv]
        smx[(SUM_OFF + b * 2048) / 4 + q * 64 + rmv] =
            (fsum2(a0) + fsum2(a1)) + (fsum2(a2) + fsum2(a3));

        // re-arm my stripe barrier AFTER the hot path (safe: precedes our
        // send -> precedes source's t+1 wait -> precedes next arrival here)
        if (t && !isLocal && lane == 0 && w < 8)
            asm volatile("mbarrier.arrive.expect_tx.shared.b64 _, [%0], %1;"
                         :: "r"(mbq), "r"(256) : "memory");

        // ---- producer/consumer split on ALTERNATING barriers 2+b ----
        if (w < 14) {
            asm volatile("bar.arrive %0, 512;" :: "r"(2 + b) : "memory");
        } else {
            asm volatile("bar.sync %0, 512;" :: "r"(2 + b) : "memory");

            // ---- reduce 8 partials for my row (same tree as R13) ----
            const float* su = smx + (SUM_OFF + b * 2048) / 4 + erow;
            float p0 = su[0*64], p1 = su[1*64], p2 = su[2*64], p3 = su[3*64];
            float p4 = su[4*64], p5 = su[5*64], p6 = su[6*64], p7 = su[7*64];
            float acc = ((p0 + p1) + (p2 + p3)) + ((p4 + p5) + (p6 + p7));

            // ---- epilogue: EXACT R13 expressions ----
            float I_E = 0.382f  + 0.21f * sE + 3.0f * acc - sI;  // LAMBDA=0
            float rE = Hfun(I_E, 310.0f, 125.0f, 0.16f,  1e9f);
            float dE = -sE * 0.01f + (1.0f - sE) * 6.41e-4f * rE + 0.01f * vc;
            float dI = -sI * 0.1f  + 1.0e-3f * rI + 0.01f * vc;
            sE = fmaf(1e-4f, dE, sE);
            sI = fmaf(1e-4f, dI, sI);

            // stage new S_E
            smx[(STG_OFF + b * 256) / 4 + erow] = sE;

            asm volatile("bar.sync 1, 64;" ::: "memory");   // warps 14-15

            // unblock local-stripe warps ASAP (release; consumers acquire)
            if (tid == 448)
                asm volatile("mbarrier.arrive.shared.b64 _, [%0];"
                             :: "r"(sb + LB_OFF + (uint32_t)(b * 8)) : "memory");

            // ---- 7 parallel 256B bulk copies (data + tx fused) ----
            if (tid < 455 && (t + 1 < NSTEPS)) {
                asm volatile("fence.proxy.async.shared::cta;" ::: "memory");
                uint32_t src = sb + (uint32_t)(STG_OFF + b * 256);
                uint32_t dst = remB + (uint32_t)(X_OFF + (b ^ 1) * 2048 + cta * 256);
                uint32_t rmb = remB + (uint32_t)(MB_OFF + (((b ^ 1) * 8) + cta) * 8);
                asm volatile(
                    "cp.async.bulk.shared::cluster.shared::cta.mbarrier::complete_tx::bytes "
                    "[%0], [%1], %2, [%3];"
                    :: "r"(dst), "r"(src), "r"(256), "r"(rmb) : "memory");
            }

            // off critical path: history + next noise
            outv[512 + (size_t)t * NREG + cta * 64 + erow] = make_float2(sE, sI);
            vc = vn;
            int t2 = t + 2; if (t2 >= NSTEPS) t2 = NSTEPS - 1;
            vn = __ldg(vofT + (size_t)t2 * NREG + cta * 64 + erow);
        }
    }

    if (epi) outv[cta * 64 + erow] = make_float2(sE, sI);

    // drain: nobody exits while peers may still write our smem
    asm volatile("barrier.cluster.arrive.aligned;" ::: "memory");
    asm volatile("barrier.cluster.wait.aligned;"   ::: "memory");
}

extern "C" void kernel_launch(void* const* d_in, const int* in_sizes, int n_in,
                              void* d_out, int out_size) {
    const float* init = nullptr;
    const float* con  = nullptr;
    const float* v    = nullptr;
    for (int i = 0; i < n_in; ++i) {
        if      (in_sizes[i] == NREG * 2)      init = (const float*)d_in[i];
        else if (in_sizes[i] == NREG * NREG)   con  = (const float*)d_in[i];
        else if (in_sizes[i] == NSTEPS * NREG) v    = (const float*)d_in[i];
    }
    rww_kernel<<<NCTAS, NTHR, SMEM_BYTES>>>(init, con, v, (float*)d_out);
    (void)out_size;
}

// round 17
// speedup vs baseline: 1.9310x; 1.0971x over previous
#include <cuda_runtime.h>
#include <cstdint>
#include <cstddef>

// RWW whole-brain sim, 8-CTA cluster, Con_Mtx register-resident.
// R17 = R16 (champion) with consumer warps remapped to the LOCAL stripe:
//   - warps 14/15 own stripe==cta; their x IS the staging buffer they wrote
//     last step (program order + bar 1,64) -> they never wait, their matvec
//     runs inside the flight window, and they are parked at bar.sync(2+b)
//     when producers arrive. Consumers can no longer be the straggler.
//   - producers w<14: stripe s=(cta+1+(w>>1))&7 (always remote), half=w&1.
//   - LB local-mbarrier machinery deleted (provably redundant now).
//   - arithmetic/reduce tree bit-identical to R13/R16 (rel_err 3.393553e-8).

#define NREG    512
#define NSTEPS  20000
#define NCTAS   8
#define NTHR    512

// smem byte map
#define X_OFF    0        // x[2][512] floats          (4096 B)
#define SUM_OFF  4096     // sums[2][512] floats       (4096 B)
#define STG_OFF  8192     // staging[2][64] floats     (512 B)
#define MB_OFF   8704     // 16 src mbarriers          (128 B)
#define SMEM_BYTES 8832

__device__ __forceinline__ unsigned long long ffma2(
    unsigned long long a, unsigned long long b, unsigned long long c) {
    unsigned long long d;
    asm("fma.rn.f32x2 %0, %1, %2, %3;" : "=l"(d) : "l"(a), "l"(b), "l"(c));
    return d;
}
__device__ __forceinline__ float fsum2(unsigned long long a) {
    float2 f = *reinterpret_cast<float2*>(&a);
    return f.x + f.y;
}
__device__ __forceinline__ void mbar_wait(uint32_t mb, uint32_t par) {
    asm volatile(
        "{\n\t"
        ".reg .pred P;\n"
        "WL_%=:\n\t"
        "mbarrier.try_wait.parity.acquire.cluster.shared::cta.b64 P, [%0], %1, 0x989680;\n\t"
        "@!P bra WL_%=;\n\t"
        "}" :: "r"(mb), "r"(par) : "memory");
}

__device__ __forceinline__ float Hfun(float I, float a, float b, float d, float bigc) {
    float x     = fmaf(a, I, -b);
    float numer = fabsf(x) + 1e-9f;
    float neg   = -d * x;
    float e     = __expf(fminf(neg, 51.0f));
    float den_s = fabsf(1.0f - e) + 1e-9f * d;
    float den_b = fabsf(1.0f - bigc * neg) + 1e-9f * d;
    float denom = (neg > 50.0f) ? den_b : den_s;
    return __fdividef(numer, denom);
}

extern __shared__ float smx[];

__global__ void __launch_bounds__(NTHR, 1) __cluster_dims__(NCTAS, 1, 1)
rww_kernel(const float* __restrict__ init_state,   // (512, 2)
           const float* __restrict__ Con,          // (512, 512) row-major
           const float* __restrict__ vofT,         // (20000, 512)
           float* __restrict__ out)                // 1024 final + 20000*1024 hist
{
    const int tid  = (int)threadIdx.x;
    const int cta  = (int)blockIdx.x;          // cluster rank
    const int lane = tid & 31;
    const int w    = tid >> 5;                 // warp 0..15
    const bool epi = (w >= 14);                // warps 14-15: epilogue + local stripe

    // stripe map: consumers own the local stripe, producers the 7 remote ones
    const int s    = epi ? cta : ((cta + 1 + (w >> 1)) & 7);   // stripe = source
    const int rmv  = epi ? ((w - 14) * 32 + lane)              // matvec row 0..63
                         : ((w & 1) * 32 + lane);
    const int erow = tid - 448;                // epilogue row 0..63 (epi only)

    uint32_t sb;
    asm("{ .reg .u64 t; cvta.to.shared.u64 t, %1; cvt.u32.u64 %0, t; }"
        : "=r"(sb) : "l"(smx));

    // ---- 16 src mbarriers [buf][src]: count=1, phase-0 tx armed ----
    if (tid < 16) {
        uint32_t mb = sb + MB_OFF + (uint32_t)(tid * 8);
        asm volatile("mbarrier.init.shared.b64 [%0], %1;" :: "r"(mb), "r"(1));
        asm volatile("mbarrier.arrive.expect_tx.shared.b64 _, [%0], %1;"
                     :: "r"(mb), "r"(256) : "memory");
    }

    // ---- Con: row cta*64+rmv, cols s*64..s*64+63 -> 32 f32x2 regs ----
    unsigned long long c64[32];
    {
        const ulonglong2* src = (const ulonglong2*)
            (Con + (size_t)(cta * 64 + rmv) * NREG + (size_t)s * 64);
        #pragma unroll
        for (int it = 0; it < 16; ++it) {
            ulonglong2 t2 = src[it];
            c64[2*it] = t2.x; c64[2*it+1] = t2.y;
        }
    }

    // ---- init x buffer 0 (contiguous; warp reads are broadcast) ----
    if (tid < NREG) smx[tid] = init_state[2 * tid];

    // ---- epilogue state (row = erow) + staging[1] bootstrap ----
    float sE = 0.0f, sI = 0.0f;
    if (epi) {
        sE = init_state[2 * (cta * 64 + erow)];
        sI = init_state[2 * (cta * 64 + erow) + 1];
        smx[(STG_OFF + 256) / 4 + erow] = sE;   // staging[1] for t=0 local read
    }

    // ---- copy threads (tid 448..454): peer smem bases ----
    uint32_t remB = 0;
    if (tid >= 448 && tid < 455) {
        int d = tid - 448;
        int dest = d + (d >= cta ? 1 : 0);
        asm("mapa.shared::cluster.u32 %0, %1, %2;" : "=r"(remB) : "r"(sb), "r"(dest));
    }

    __syncthreads();
    asm volatile("barrier.cluster.arrive.aligned;" ::: "memory");
    asm volatile("barrier.cluster.wait.aligned;"   ::: "memory");

    float vc = 0.0f, vn = 0.0f;
    if (epi) {
        vc = __ldg(vofT + cta * 64 + erow);
        vn = __ldg(vofT + NREG + cta * 64 + erow);
    }
    float2* outv = (float2*)out;

    int pb0 = 0, pb1 = 0;     // parities of my stripe barrier, per buffer

    for (int t = 0; t < NSTEPS; ++t) {
        const int b = t & 1;

        // ---- hoisted, bit-identical rI chain (no network term) ----
        float rI = 0.0f;
        if (epi) {
            float I_I = 0.2674f + 0.15f * sE - sI;
            rI = Hfun(I_I, 615.0f, 177.0f, 0.087f, 1e5f);
        }

        // ---- producers wait on their remote stripe; consumers never wait ----
        uint32_t mbq = 0;
        if (t && !epi) {
            mbq = sb + MB_OFF + (uint32_t)((b * 8 + s) * 8);
            if (b) { mbar_wait(mbq, (uint32_t)pb1); pb1 ^= 1; }
            else   { mbar_wait(mbq, (uint32_t)pb0); pb0 ^= 1; }
        }

        // ---- matvec: 64 cols of stripe s (broadcast LDS), row rmv ----
        // consumers read the staging buffer they wrote last step (local)
        const ulonglong2* x2 = epi
            ? (const ulonglong2*)((const char*)smx + STG_OFF + (b ^ 1) * 256)
            : (const ulonglong2*)((const char*)smx + X_OFF + b * 2048 + s * 256);
        unsigned long long a0 = 0ULL, a1 = 0ULL, a2 = 0ULL, a3 = 0ULL;
        #pragma unroll
        for (int it = 0; it < 8; ++it) {
            ulonglong2 xa = x2[2*it];
            ulonglong2 xb = x2[2*it+1];
            a0 = ffma2(c64[4*it+0], xa.x, a0);
            a1 = ffma2(c64[4*it+1], xa.y, a1);
            a2 = ffma2(c64[4*it+2], xb.x, a2);
            a3 = ffma2(c64[4*it+3], xb.y, a3);
        }
        // partial for (row rmv, stripe s) -> sums[b][s*64 + rmv]
        smx[(SUM_OFF + b * 2048) / 4 + s * 64 + rmv] =
            (fsum2(a0) + fsum2(a1)) + (fsum2(a2) + fsum2(a3));

        // re-arm my stripe barrier (one per barrier: even producer warps,
        // lane 0). Safe: precedes our bar.arrive -> our send -> source's
        // next wait -> next arrival here.
        if (t && !epi && (w & 1) == 0 && lane == 0)
            asm volatile("mbarrier.arrive.expect_tx.shared.b64 _, [%0], %1;"
                         :: "r"(mbq), "r"(256) : "memory");

        // ---- producer/consumer split on ALTERNATING barriers 2+b ----
        if (!epi) {
            asm volatile("bar.arrive %0, 512;" :: "r"(2 + b) : "memory");
        } else {
            asm volatile("bar.sync %0, 512;" :: "r"(2 + b) : "memory");

            // ---- reduce 8 partials for my row (same tree as R13) ----
            const float* su = smx + (SUM_OFF + b * 2048) / 4 + erow;
            float p0 = su[0*64], p1 = su[1*64], p2 = su[2*64], p3 = su[3*64];
            float p4 = su[4*64], p5 = su[5*64], p6 = su[6*64], p7 = su[7*64];
            float acc = ((p0 + p1) + (p2 + p3)) + ((p4 + p5) + (p6 + p7));

            // ---- epilogue: EXACT R13 expressions ----
            float I_E = 0.382f  + 0.21f * sE + 3.0f * acc - sI;  // LAMBDA=0
            float rE = Hfun(I_E, 310.0f, 125.0f, 0.16f,  1e9f);
            float dE = -sE * 0.01f + (1.0f - sE) * 6.41e-4f * rE + 0.01f * vc;
            float dI = -sI * 0.1f  + 1.0e-3f * rI + 0.01f * vc;
            sE = fmaf(1e-4f, dE, sE);
            sI = fmaf(1e-4f, dI, sI);

            // stage new S_E (read locally next step + copy payload)
            smx[(STG_OFF + b * 256) / 4 + erow] = sE;

            asm volatile("bar.sync 1, 64;" ::: "memory");   // warps 14-15

            // ---- 7 parallel 256B bulk copies (data + tx fused) ----
            if (tid < 455 && (t + 1 < NSTEPS)) {
                asm volatile("fence.proxy.async.shared::cta;" ::: "memory");
                uint32_t src = sb + (uint32_t)(STG_OFF + b * 256);
                uint32_t dst = remB + (uint32_t)(X_OFF + (b ^ 1) * 2048 + cta * 256);
                uint32_t rmb = remB + (uint32_t)(MB_OFF + (((b ^ 1) * 8) + cta) * 8);
                asm volatile(
                    "cp.async.bulk.shared::cluster.shared::cta.mbarrier::complete_tx::bytes "
                    "[%0], [%1], %2, [%3];"
                    :: "r"(dst), "r"(src), "r"(256), "r"(rmb) : "memory");
            }

            // off critical path: history + next noise
            outv[512 + (size_t)t * NREG + cta * 64 + erow] = make_float2(sE, sI);
            vc = vn;
            int t2 = t + 2; if (t2 >= NSTEPS) t2 = NSTEPS - 1;
            vn = __ldg(vofT + (size_t)t2 * NREG + cta * 64 + erow);
        }
    }

    if (epi) outv[cta * 64 + erow] = make_float2(sE, sI);

    // drain: nobody exits while peers may still write our smem
    asm volatile("barrier.cluster.arrive.aligned;" ::: "memory");
    asm volatile("barrier.cluster.wait.aligned;"   ::: "memory");
}

extern "C" void kernel_launch(void* const* d_in, const int* in_sizes, int n_in,
                              void* d_out, int out_size) {
    const float* init = nullptr;
    const float* con  = nullptr;
    const float* v    = nullptr;
    for (int i = 0; i < n_in; ++i) {
        if      (in_sizes[i] == NREG * 2)      init = (const float*)d_in[i];
        else if (in_sizes[i] == NREG * NREG)   con  = (const float*)d_in[i];
        else if (in_sizes[i] == NSTEPS * NREG) v    = (const float*)d_in[i];
    }
    rww_kernel<<<NCTAS, NTHR, SMEM_BYTES>>>(init, con, v, (float*)d_out);
    (void)out_size;
}